// round 8
// baseline (speedup 1.0000x reference)
#include <cuda_runtime.h>
#include <math.h>

// Shapes fixed by the reference:
//  B=16,T=32 -> BT=512 ; NP=8, NG=4, J=14, H=256
#define BT      512
#define HEAT_N  (512 * 256 * 256)    // 33,554,432 floats
#define N4      (HEAT_N / 4)         // 8,388,608 float4
#define NBLK    1024
#define WM      31                   // heat weight: match blocks (one fewer iter)
#define WH      32                   // heat weight: heat-only blocks
#define TOTW    (512 * WM + 512 * WH)   // 32256

#define INV_HEAT (1.0f / (float)HEAT_N)
#define INV_BT   (1.0f / 512.0f)
#define INV_POSE (1.0f / (512.0f * 8.0f * 14.0f))

// Prefetch buffer layout (floats): pp 336 | gp 168 | pc 16 | gc 8 | sc 8 |
//                                  po 16 | go 8 | ps 32 | gs 16  = 608 floats
#define PF_PP 0
#define PF_GP 336
#define PF_PC 504
#define PF_GC 520
#define PF_SC 528
#define PF_PO 536
#define PF_GO 552
#define PF_PS 560
#define PF_GS 592
#define PF_FLOATS 608
#define PF_CHUNKS 152               // 608 floats = 152 x 16B

__device__ float        g_part[NBLK];   // per-block contribution (pre-scaled)
__device__ unsigned int g_count;        // completion counter (self-resetting)

// Monotone float->uint map: equal floats -> equal keys, order preserved.
__device__ __forceinline__ unsigned f2ord(float v) {
    unsigned u = __float_as_uint(v);
    return (u & 0x80000000u) ? ~u : (u | 0x80000000u);
}

__device__ __forceinline__ unsigned long long umin64(unsigned long long a,
                                                     unsigned long long b) {
    return a < b ? a : b;
}

// Lexicographic rank -> k-permutation of range(8), k=4 (itertools order).
__device__ __forceinline__ void decode_perm(int r, int* p) {
    const int divs[4] = {210, 30, 5, 1};
    unsigned mask = 0xFFu;
#pragma unroll
    for (int k = 0; k < 4; k++) {
        int d = r / divs[k];
        r -= d * divs[k];
        unsigned m = mask;
#pragma unroll
        for (int q = 0; q < 7; q++)
            if (q < d) m &= (m - 1);
        int idx = __ffs(m) - 1;
        mask &= ~(1u << idx);
        p[k] = idx;
    }
}

__global__ void __launch_bounds__(256, 7)
k_fused(const float4* __restrict__ ha,   // hor_heatmap as float4
        const float4* __restrict__ hb,   // gt_heatmap  as float4
        const float* __restrict__ po_all,   // hor_offset  (BT,8,2)
        const float* __restrict__ ps_all,   // hor_bsize   (BT,8,4)
        const float* __restrict__ pc_all,   // hor_center  (BT,8,2)
        const float* __restrict__ sc_all,   // scores      (BT,8)
        const float* __restrict__ pp_all,   // x_pose3d    (BT,8,14,3)
        const float* __restrict__ gs_all,   // gt_boxes_wh (BT,4,4)
        const float* __restrict__ go_all,   // gt_offset   (BT,4,2)
        const float* __restrict__ gc_all,   // gt_center   (BT,4,2)
        const float* __restrict__ gp_all,   // gt_pose3d   (BT,4,14,3)
        float* __restrict__ out)
{
    const int bid = blockIdx.x;
    const int t   = threadIdx.x;

    __shared__ float sred[256];
    __shared__ float s_pref[PF_FLOATS];
    __shared__ float sCb[32], sCp[32];
    __shared__ unsigned long long skB[64], skP[64];
    __shared__ int   s_pb[4], s_pq[4];
    __shared__ float s_heat;
    __shared__ bool  isLast;

    // ==================================================================
    // Step 0 (blocks 0..511): fire-and-forget cp.async prefetch of the
    // whole 2.4KB match working set. Completes under the heat stream.
    // ==================================================================
    if (bid < BT && t < PF_CHUNKS) {
        const int bt = bid;
        const float* src;
        if      (t <  84) src = pp_all + bt * 336 + t * 4;
        else if (t < 126) src = gp_all + bt * 168 + (t -  84) * 4;
        else if (t < 130) src = pc_all + bt * 16  + (t - 126) * 4;
        else if (t < 132) src = gc_all + bt * 8   + (t - 130) * 4;
        else if (t < 134) src = sc_all + bt * 8   + (t - 132) * 4;
        else if (t < 138) src = po_all + bt * 16  + (t - 134) * 4;
        else if (t < 140) src = go_all + bt * 8   + (t - 138) * 4;
        else if (t < 148) src = ps_all + bt * 32  + (t - 140) * 4;
        else              src = gs_all + bt * 16  + (t - 148) * 4;
        unsigned dst = (unsigned)__cvta_generic_to_shared(s_pref + t * 4);
        asm volatile("cp.async.cg.shared.global [%0], [%1], 16;" ::
                     "r"(dst), "l"(src));
        asm volatile("cp.async.commit_group;");
    }

    // ==================================================================
    // Phase 1 (ALL blocks): heatmap MSE, full width from cycle 0.
    // 31:32 skew gives match blocks one fewer iteration (~1.3us) to pay
    // for their match compute.
    // ==================================================================
    {
        long long cw0 = (bid < BT)
                            ? (long long)bid * WM
                            : (long long)BT * WM + (long long)(bid - BT) * WH;
        int w = (bid < BT) ? WM : WH;
        int s = (int)(cw0 * (long long)N4 / TOTW);
        int e = (int)((cw0 + w) * (long long)N4 / TOTW);

        float acc = 0.f;
        for (int i = s + t; i < e; i += 256) {
            float4 x = ha[i];
            float4 y = hb[i];
            float dx = x.x - y.x, dy = x.y - y.y, dz = x.z - y.z, dw = x.w - y.w;
            acc += dx * dx + dy * dy + dz * dz + dw * dw;
        }
        sred[t] = acc;
        __syncthreads();
#pragma unroll
        for (int o = 128; o > 0; o >>= 1) {
            if (t < o) sred[t] += sred[t + o];
            __syncthreads();
        }
        if (t == 0) s_heat = sred[0];
        // (sync below, before sred reuse)
    }

    // ==================================================================
    // Phase 2 (blocks 0..511): match entirely from shared memory.
    // ==================================================================
    if (bid < BT) {
        asm volatile("cp.async.wait_group 0;");
        __syncthreads();              // prefetch visible + sred reusable

        const float* s_pp = s_pref + PF_PP;
        const float* s_gp = s_pref + PF_GP;

        // Cost matrices: entry e = t>>3 (i = e>>2, j = e&3), part q = t&7,
        // each part sums 6 of the 42 pose terms.
        {
            int e = t >> 3, q = t & 7;
            int i = e >> 2, j = e & 3;
            float s = 0.f;
            int k0 = q * 6;
#pragma unroll
            for (int c = 0; c < 6; c++) {
                int k = k0 + c;
                if (k < 42) {
                    float d = s_pp[i * 42 + k] - s_gp[j * 42 + k];
                    s += d * d;
                }
            }
            sred[t] = s;
            if (q == 0) {
                float dx = s_pref[PF_PC + 2 * i]     - s_pref[PF_GC + 2 * j];
                float dy = s_pref[PF_PC + 2 * i + 1] - s_pref[PF_GC + 2 * j + 1];
                sCb[e] = sqrtf(dx * dx + dy * dy) - s_pref[PF_SC + i];
            }
        }
        __syncthreads();
        if (t < 32) {
            float s = 0.f;
#pragma unroll
            for (int q = 0; q < 8; q++) s += sred[t * 8 + q];
            sCp[t] = sqrtf(s);
        }
        __syncthreads();

        // Sweep all 1680 combos: 56 (d0,d1)-prefixes x 30.
        // rank = ((d0*7+d1)*6+d2)*5+d3 (itertools lexicographic);
        // min over (orderedFloat<<32 | rank) = exact first-argmin.
        if (t < 64) { skB[t] = ~0ull; skP[t] = ~0ull; }
        __syncthreads();
        if (t < 56) {
            int d0 = t / 7, d1 = t - d0 * 7;
            int i0 = d0;
            int i1 = d1 + (d1 >= d0);
            int a1 = min(i0, i1), b1 = max(i0, i1);
            float sb01 = sCb[i0 * 4 + 0] + sCb[i1 * 4 + 1];
            float sp01 = sCp[i0 * 4 + 0] + sCp[i1 * 4 + 1];
            unsigned long long kb = ~0ull, kp = ~0ull;
            int rbase = t * 30;
#pragma unroll
            for (int d2 = 0; d2 < 6; d2++) {
                int i2 = d2;
                i2 += (i2 >= a1);
                i2 += (i2 >= b1);
                float sb2 = sb01 + sCb[i2 * 4 + 2];
                float sp2 = sp01 + sCp[i2 * 4 + 2];
                int a2, b2, c2;
                if (i2 < a1)      { a2 = i2; b2 = a1; c2 = b1; }
                else if (i2 < b1) { a2 = a1; b2 = i2; c2 = b1; }
                else              { a2 = a1; b2 = b1; c2 = i2; }
#pragma unroll
                for (int d3 = 0; d3 < 5; d3++) {
                    int i3 = d3;
                    i3 += (i3 >= a2);
                    i3 += (i3 >= b2);
                    i3 += (i3 >= c2);
                    float tb = sb2 + sCb[i3 * 4 + 3];
                    float tp = sp2 + sCp[i3 * 4 + 3];
                    unsigned r = (unsigned)(rbase + d2 * 5 + d3);
                    kb = umin64(kb, ((unsigned long long)f2ord(tb) << 32) | r);
                    kp = umin64(kp, ((unsigned long long)f2ord(tp) << 32) | r);
                }
            }
            skB[t] = kb; skP[t] = kp;
        }
        __syncthreads();
        if (t < 32) {
            unsigned long long kb = umin64(skB[t], skB[t + 32]);
            unsigned long long kp = umin64(skP[t], skP[t + 32]);
#pragma unroll
            for (int o = 16; o > 0; o >>= 1) {
                kb = umin64(kb, __shfl_xor_sync(0xffffffffu, kb, o));
                kp = umin64(kp, __shfl_xor_sync(0xffffffffu, kp, o));
            }
            if (t == 0) {
                int pb[4], pq[4];
                decode_perm((int)(kb & 0xFFFFFFFFu), pb);
                decode_perm((int)(kp & 0xFFFFFFFFu), pq);
#pragma unroll
                for (int j = 0; j < 4; j++) { s_pb[j] = pb[j]; s_pq[j] = pq[j]; }
            }
        }
        __syncthreads();

        // Tail losses: 168 pose terms + 24 box terms, all from shared.
        {
            float v = 0.f;
            if (t < 168) {
                int j = t / 42, k = t - j * 42;
                float d = s_pp[s_pq[j] * 42 + k] - s_gp[t];
                v = d * d * INV_POSE;
            } else if (t < 192) {
                int u = t - 168;
                int j = u / 6, w = u - j * 6;
                int i = s_pb[j];
                if (w < 2) {
                    v = 0.5f * INV_BT * fabsf(s_pref[PF_PO + i * 2 + w] -
                                              s_pref[PF_GO + j * 2 + w]);
                } else {
                    int k = w - 2;
                    v = 0.25f * INV_BT * fabsf(s_pref[PF_PS + i * 4 + k] -
                                               s_pref[PF_GS + j * 4 + k]);
                }
            }
            sred[t] = v;
        }
        __syncthreads();
#pragma unroll
        for (int o = 128; o > 0; o >>= 1) {
            if (t < o) sred[t] += sred[t + o];
            __syncthreads();
        }
        if (t == 0) g_part[bid] = s_heat * INV_HEAT + sred[0];
    } else {
        __syncthreads();              // pair with nothing needed; keep uniform
        if (t == 0) g_part[bid] = s_heat * INV_HEAT;
    }

    // ==================================================================
    // Phase 3: last block to arrive combines (threadFenceReduction).
    // Single 1024-float read round.
    // ==================================================================
    if (t == 0) {
        __threadfence();
        unsigned old = atomicAdd(&g_count, 1u);
        isLast = (old == NBLK - 1);
    }
    __syncthreads();

    if (isLast) {
        __threadfence();
        float v = g_part[t] + g_part[t + 256] + g_part[t + 512] + g_part[t + 768];
        sred[t] = v;
        __syncthreads();
#pragma unroll
        for (int o = 128; o > 0; o >>= 1) {
            if (t < o) sred[t] += sred[t + o];
            __syncthreads();
        }
        if (t == 0) {
            out[0]  = sred[0];
            g_count = 0;              // reset for next graph replay
        }
    }
}

extern "C" void kernel_launch(void* const* d_in, const int* in_sizes, int n_in,
                              void* d_out, int out_size) {
    const float* hor_heatmap = (const float*)d_in[0];
    const float* hor_offset  = (const float*)d_in[1];
    const float* hor_bsize   = (const float*)d_in[2];
    const float* hor_center  = (const float*)d_in[3];
    const float* scores      = (const float*)d_in[4];
    const float* x_pose3d    = (const float*)d_in[5];
    const float* gt_heatmap  = (const float*)d_in[6];
    const float* gt_boxes_wh = (const float*)d_in[7];
    const float* gt_offset   = (const float*)d_in[8];
    const float* gt_center   = (const float*)d_in[9];
    const float* gt_pose3d   = (const float*)d_in[10];

    k_fused<<<NBLK, 256>>>((const float4*)hor_heatmap, (const float4*)gt_heatmap,
                           hor_offset, hor_bsize, hor_center, scores, x_pose3d,
                           gt_boxes_wh, gt_offset, gt_center, gt_pose3d,
                           (float*)d_out);
}

// round 9
// speedup vs baseline: 1.0309x; 1.0309x over previous
#include <cuda_runtime.h>
#include <math.h>

// Shapes fixed by the reference:
//  B=16,T=32 -> BT=512 ; NP=8, NG=4, J=14, H=256
#define BT      512
#define HEAT_N  (512 * 256 * 256)    // 33,554,432 floats
#define HEAT_BLOCKS 1024

#define INV_HEAT (1.0f / (float)HEAT_N)
#define INV_BT   (1.0f / 512.0f)
#define INV_POSE (1.0f / (512.0f * 8.0f * 14.0f))

// Staging buffer layout (floats): pp 336 | gp 168 | pc 16 | gc 8 | sc 8 |
//                                 po 16 | go 8 | ps 32 | gs 16  = 608 floats
#define PF_PP 0
#define PF_GP 336
#define PF_PC 504
#define PF_GC 520
#define PF_SC 528
#define PF_PO 536
#define PF_GO 552
#define PF_PS 560
#define PF_GS 592
#define PF_FLOATS 608
#define PF_CHUNKS 152               // 608 floats = 152 x float4

__device__ float g_heat_part[HEAT_BLOCKS];
__device__ float g_match[BT];

// ---------------------------------------------------------------------------
// Kernel 1: heatmap MSE — EXACT replica of the R1 kernel measured at
// 43.4us / 6.27TB/s. Do not touch.
// ---------------------------------------------------------------------------
__global__ void k_heat(const float4* __restrict__ a, const float4* __restrict__ b) {
    const int n4 = HEAT_N / 4;
    float acc = 0.f;
    for (int i = blockIdx.x * blockDim.x + threadIdx.x; i < n4;
         i += gridDim.x * blockDim.x) {
        float4 x = a[i];
        float4 y = b[i];
        float dx = x.x - y.x, dy = x.y - y.y, dz = x.z - y.z, dw = x.w - y.w;
        acc += dx * dx + dy * dy + dz * dz + dw * dw;
    }
    __shared__ float s[256];
    s[threadIdx.x] = acc;
    __syncthreads();
    for (int o = 128; o > 0; o >>= 1) {
        if (threadIdx.x < o) s[threadIdx.x] += s[threadIdx.x + o];
        __syncthreads();
    }
    if (threadIdx.x == 0) g_heat_part[blockIdx.x] = s[0];
}

// Monotone float->uint map: equal floats -> equal keys, order preserved.
__device__ __forceinline__ unsigned f2ord(float v) {
    unsigned u = __float_as_uint(v);
    return (u & 0x80000000u) ? ~u : (u | 0x80000000u);
}

__device__ __forceinline__ unsigned long long umin64(unsigned long long a,
                                                     unsigned long long b) {
    return a < b ? a : b;
}

// Lexicographic rank -> k-permutation of range(8), k=4 (itertools order).
__device__ __forceinline__ void decode_perm(int r, int* p) {
    const int divs[4] = {210, 30, 5, 1};
    unsigned mask = 0xFFu;
#pragma unroll
    for (int k = 0; k < 4; k++) {
        int d = r / divs[k];
        r -= d * divs[k];
        unsigned m = mask;
#pragma unroll
        for (int q = 0; q < 7; q++)
            if (q < d) m &= (m - 1);
        int idx = __ffs(m) - 1;
        mask &= ~(1u << idx);
        p[k] = idx;
    }
}

// ---------------------------------------------------------------------------
// Kernel 2: per-(b,t) match, one block of 256 threads per cell, staged
// through shared memory. All stages parallel; no serial thread-0 work.
// ---------------------------------------------------------------------------
__global__ void __launch_bounds__(256)
k_match(const float* __restrict__ po_all,   // hor_offset  (BT,8,2)
        const float* __restrict__ ps_all,   // hor_bsize   (BT,8,4)
        const float* __restrict__ pc_all,   // hor_center  (BT,8,2)
        const float* __restrict__ sc_all,   // scores      (BT,8)
        const float* __restrict__ pp_all,   // x_pose3d    (BT,8,14,3)
        const float* __restrict__ gs_all,   // gt_boxes_wh (BT,4,4)
        const float* __restrict__ go_all,   // gt_offset   (BT,4,2)
        const float* __restrict__ gc_all,   // gt_center   (BT,4,2)
        const float* __restrict__ gp_all)   // gt_pose3d   (BT,4,14,3)
{
    const int bt = blockIdx.x;
    const int t  = threadIdx.x;

    __shared__ float s_pref[PF_FLOATS];
    __shared__ float sred[256];
    __shared__ float sCb[32], sCp[32];
    __shared__ unsigned long long skB[64], skP[64];
    __shared__ int   s_pb[4], s_pq[4];

    // Cooperative staging: one float4 per thread (all sources 16B aligned).
    if (t < PF_CHUNKS) {
        const float* src;
        if      (t <  84) src = pp_all + bt * 336 + t * 4;
        else if (t < 126) src = gp_all + bt * 168 + (t -  84) * 4;
        else if (t < 130) src = pc_all + bt * 16  + (t - 126) * 4;
        else if (t < 132) src = gc_all + bt * 8   + (t - 130) * 4;
        else if (t < 134) src = sc_all + bt * 8   + (t - 132) * 4;
        else if (t < 138) src = po_all + bt * 16  + (t - 134) * 4;
        else if (t < 140) src = go_all + bt * 8   + (t - 138) * 4;
        else if (t < 148) src = ps_all + bt * 32  + (t - 140) * 4;
        else              src = gs_all + bt * 16  + (t - 148) * 4;
        float4 v = *(const float4*)src;
        *(float4*)(s_pref + t * 4) = v;
    }
    __syncthreads();

    const float* s_pp = s_pref + PF_PP;
    const float* s_gp = s_pref + PF_GP;

    // Cost matrices: entry e = t>>3 (i = e>>2, j = e&3), part q = t&7,
    // each part sums 6 of the 42 pose terms.
    {
        int e = t >> 3, q = t & 7;
        int i = e >> 2, j = e & 3;
        float s = 0.f;
        int k0 = q * 6;
#pragma unroll
        for (int c = 0; c < 6; c++) {
            int k = k0 + c;
            if (k < 42) {
                float d = s_pp[i * 42 + k] - s_gp[j * 42 + k];
                s += d * d;
            }
        }
        sred[t] = s;
        if (q == 0) {
            float dx = s_pref[PF_PC + 2 * i]     - s_pref[PF_GC + 2 * j];
            float dy = s_pref[PF_PC + 2 * i + 1] - s_pref[PF_GC + 2 * j + 1];
            sCb[e] = sqrtf(dx * dx + dy * dy) - s_pref[PF_SC + i];
        }
    }
    __syncthreads();
    if (t < 32) {
        float s = 0.f;
#pragma unroll
        for (int q = 0; q < 8; q++) s += sred[t * 8 + q];
        sCp[t] = sqrtf(s);
    }
    __syncthreads();

    // Sweep all 1680 combos: 56 (d0,d1)-prefixes x 30 each.
    // rank = ((d0*7+d1)*6+d2)*5+d3 (itertools lexicographic order);
    // min over (orderedFloat<<32 | rank) = exact first-argmin.
    if (t < 64) { skB[t] = ~0ull; skP[t] = ~0ull; }
    __syncthreads();
    if (t < 56) {
        int d0 = t / 7, d1 = t - d0 * 7;
        int i0 = d0;
        int i1 = d1 + (d1 >= d0);
        int a1 = min(i0, i1), b1 = max(i0, i1);
        float sb01 = sCb[i0 * 4 + 0] + sCb[i1 * 4 + 1];
        float sp01 = sCp[i0 * 4 + 0] + sCp[i1 * 4 + 1];
        unsigned long long kb = ~0ull, kp = ~0ull;
        int rbase = t * 30;
#pragma unroll
        for (int d2 = 0; d2 < 6; d2++) {
            int i2 = d2;
            i2 += (i2 >= a1);
            i2 += (i2 >= b1);
            float sb2 = sb01 + sCb[i2 * 4 + 2];
            float sp2 = sp01 + sCp[i2 * 4 + 2];
            int a2, b2, c2;
            if (i2 < a1)      { a2 = i2; b2 = a1; c2 = b1; }
            else if (i2 < b1) { a2 = a1; b2 = i2; c2 = b1; }
            else              { a2 = a1; b2 = b1; c2 = i2; }
#pragma unroll
            for (int d3 = 0; d3 < 5; d3++) {
                int i3 = d3;
                i3 += (i3 >= a2);
                i3 += (i3 >= b2);
                i3 += (i3 >= c2);
                float tb = sb2 + sCb[i3 * 4 + 3];
                float tp = sp2 + sCp[i3 * 4 + 3];
                unsigned r = (unsigned)(rbase + d2 * 5 + d3);
                kb = umin64(kb, ((unsigned long long)f2ord(tb) << 32) | r);
                kp = umin64(kp, ((unsigned long long)f2ord(tp) << 32) | r);
            }
        }
        skB[t] = kb; skP[t] = kp;
    }
    __syncthreads();
    if (t < 32) {
        unsigned long long kb = umin64(skB[t], skB[t + 32]);
        unsigned long long kp = umin64(skP[t], skP[t + 32]);
#pragma unroll
        for (int o = 16; o > 0; o >>= 1) {
            kb = umin64(kb, __shfl_xor_sync(0xffffffffu, kb, o));
            kp = umin64(kp, __shfl_xor_sync(0xffffffffu, kp, o));
        }
        if (t == 0) {
            int pb[4], pq[4];
            decode_perm((int)(kb & 0xFFFFFFFFu), pb);
            decode_perm((int)(kp & 0xFFFFFFFFu), pq);
#pragma unroll
            for (int j = 0; j < 4; j++) { s_pb[j] = pb[j]; s_pq[j] = pq[j]; }
        }
    }
    __syncthreads();

    // Tail losses: 168 pose terms + 24 box terms, all from shared.
    {
        float v = 0.f;
        if (t < 168) {
            int j = t / 42, k = t - j * 42;
            float d = s_pp[s_pq[j] * 42 + k] - s_gp[t];
            v = d * d * INV_POSE;
        } else if (t < 192) {
            int u = t - 168;
            int j = u / 6, w = u - j * 6;
            int i = s_pb[j];
            if (w < 2) {
                v = 0.5f * INV_BT * fabsf(s_pref[PF_PO + i * 2 + w] -
                                          s_pref[PF_GO + j * 2 + w]);
            } else {
                int k = w - 2;
                v = 0.25f * INV_BT * fabsf(s_pref[PF_PS + i * 4 + k] -
                                           s_pref[PF_GS + j * 4 + k]);
            }
        }
        sred[t] = v;
    }
    __syncthreads();
#pragma unroll
    for (int o = 128; o > 0; o >>= 1) {
        if (t < o) sred[t] += sred[t + o];
        __syncthreads();
    }
    if (t == 0) g_match[bt] = sred[0];
}

// ---------------------------------------------------------------------------
// Kernel 3: combine partials into the scalar loss.
// ---------------------------------------------------------------------------
__global__ void k_final(float* __restrict__ out) {
    int t = threadIdx.x;
    float v = g_heat_part[t] + g_heat_part[t + 256] +
              g_heat_part[t + 512] + g_heat_part[t + 768];
    v *= INV_HEAT;
    v += g_match[t] + g_match[t + 256];

    __shared__ float s[256];
    s[t] = v;
    __syncthreads();
#pragma unroll
    for (int o = 128; o > 0; o >>= 1) {
        if (t < o) s[t] += s[t + o];
        __syncthreads();
    }
    if (t == 0) out[0] = s[0];
}

// ---------------------------------------------------------------------------
extern "C" void kernel_launch(void* const* d_in, const int* in_sizes, int n_in,
                              void* d_out, int out_size) {
    const float* hor_heatmap = (const float*)d_in[0];
    const float* hor_offset  = (const float*)d_in[1];
    const float* hor_bsize   = (const float*)d_in[2];
    const float* hor_center  = (const float*)d_in[3];
    const float* scores      = (const float*)d_in[4];
    const float* x_pose3d    = (const float*)d_in[5];
    const float* gt_heatmap  = (const float*)d_in[6];
    const float* gt_boxes_wh = (const float*)d_in[7];
    const float* gt_offset   = (const float*)d_in[8];
    const float* gt_center   = (const float*)d_in[9];
    const float* gt_pose3d   = (const float*)d_in[10];

    // k_match first: it's tiny and independent of k_heat; any launch overlap
    // the scheduler grants is free. k_final depends on both.
    k_match<<<BT, 256>>>(hor_offset, hor_bsize, hor_center, scores, x_pose3d,
                         gt_boxes_wh, gt_offset, gt_center, gt_pose3d);
    k_heat<<<HEAT_BLOCKS, 256>>>((const float4*)hor_heatmap,
                                 (const float4*)gt_heatmap);
    k_final<<<1, 256>>>((float*)d_out);
}